// round 1
// baseline (speedup 1.0000x reference)
#include <cuda_runtime.h>
#include <cstdint>
#include <cstdio>

#define L_SEQ 4096
#define DIM   1024
#define NHEAD 16
#define HDIM  64
#define PDIM  128
#define BATCH 4

// ---------------- scratch (device globals; no allocation allowed) ----------------
__device__ float g_Q [(size_t)BATCH * L_SEQ * DIM];   // 64 MB  Q after rope, [B,L,D]
__device__ float g_KF[BATCH * 128 * DIM];             // 2 MB   K (first 128 tokens, roped)
__device__ float g_VF[BATCH * 128 * DIM];             // 2 MB   V (first 128 tokens)
__device__ float g_Kp[BATCH * NHEAD * PDIM * HDIM];   // 2 MB   projected K
__device__ float g_Vp[BATCH * NHEAD * PDIM * HDIM];   // 2 MB   projected V
__device__ float g_AT[(size_t)BATCH * L_SEQ * DIM];   // 64 MB  attention output [B,L,D]

// ---------------- packed f32x2 helpers (Blackwell full-rate fp32 path) ----------------
__device__ __forceinline__ unsigned long long pk2(float lo, float hi) {
    unsigned long long r;
    asm("mov.b64 %0,{%1,%2};" : "=l"(r) : "f"(lo), "f"(hi));
    return r;
}
__device__ __forceinline__ unsigned long long dup2(float v) {
    unsigned long long r;
    asm("mov.b64 %0,{%1,%1};" : "=l"(r) : "f"(v));
    return r;
}
__device__ __forceinline__ void fma2(unsigned long long& d, unsigned long long a, unsigned long long b) {
    asm("fma.rn.f32x2 %0,%1,%2,%0;" : "+l"(d) : "l"(a), "l"(b));
}
__device__ __forceinline__ float2 upk(unsigned long long v) {
    float lo, hi;
    asm("mov.b64 {%0,%1},%2;" : "=f"(lo), "=f"(hi) : "l"(v));
    return make_float2(lo, hi);
}

// ---------------- SGEMM: C[M,N] = A[M,K] @ B[N,K]^T (both row-major, K-major) ----------------
// BM=BN=128, BK=16, 256 threads, 8x8 per thread, packed f32x2 accumulate.
// ROPE: apply rotary embedding in epilogue (pairs of consecutive columns; head dim 64).
// GATHER: A rows map grow -> (grow>>7)*L_SEQ + (grow&127)  (first-128-tokens gather).
constexpr int BM = 128, BN = 128, BK = 16;
constexpr int LDT = BM + 4;   // padded smem row (keeps 16B alignment, breaks most conflicts)

template<int ROPE, int GATHER>
__global__ __launch_bounds__(256, 2)
void sgemm_nt(const float* __restrict__ A, const float* __restrict__ B,
              float* __restrict__ C, int M, int N, int K,
              const float* __restrict__ cosT, const float* __restrict__ sinT,
              int lmask)
{
    __shared__ float As[BK][LDT];
    __shared__ float Bs[BK][LDT];

    const int tid = threadIdx.x;
    const int tx = tid & 15;          // column group 0..15
    const int ty = tid >> 4;          // row group 0..15
    const int brow = blockIdx.y * BM;
    const int bcol = blockIdx.x * BN;

    unsigned long long acc[8][4];
#pragma unroll
    for (int i = 0; i < 8; i++)
#pragma unroll
        for (int j = 0; j < 4; j++) acc[i][j] = 0ULL;

    for (int k0 = 0; k0 < K; k0 += BK) {
        // load A tile [BM x BK] (coalesced float4), store transposed
#pragma unroll
        for (int it = 0; it < 2; it++) {
            int idx = tid + it * 256;        // 0..511
            int r   = idx >> 2;              // 0..127
            int c4  = (idx & 3) * 4;         // 0,4,8,12
            int grow = brow + r;
            int arow = GATHER ? ((grow >> 7) * L_SEQ + (grow & 127)) : grow;
            float4 v = *(const float4*)(A + (size_t)arow * K + k0 + c4);
            As[c4 + 0][r] = v.x; As[c4 + 1][r] = v.y;
            As[c4 + 2][r] = v.z; As[c4 + 3][r] = v.w;
        }
        // load B tile [BN x BK]
#pragma unroll
        for (int it = 0; it < 2; it++) {
            int idx = tid + it * 256;
            int r   = idx >> 2;
            int c4  = (idx & 3) * 4;
            float4 v = *(const float4*)(B + (size_t)(bcol + r) * K + k0 + c4);
            Bs[c4 + 0][r] = v.x; Bs[c4 + 1][r] = v.y;
            Bs[c4 + 2][r] = v.z; Bs[c4 + 3][r] = v.w;
        }
        __syncthreads();

#pragma unroll
        for (int kk = 0; kk < BK; kk++) {
            float4 a0 = *(const float4*)&As[kk][ty * 8];
            float4 a1 = *(const float4*)&As[kk][ty * 8 + 4];
            float4 b0 = *(const float4*)&Bs[kk][tx * 8];
            float4 b1 = *(const float4*)&Bs[kk][tx * 8 + 4];
            unsigned long long bp[4];
            bp[0] = pk2(b0.x, b0.y); bp[1] = pk2(b0.z, b0.w);
            bp[2] = pk2(b1.x, b1.y); bp[3] = pk2(b1.z, b1.w);
            float av[8] = {a0.x, a0.y, a0.z, a0.w, a1.x, a1.y, a1.z, a1.w};
#pragma unroll
            for (int i = 0; i < 8; i++) {
                unsigned long long ad = dup2(av[i]);
#pragma unroll
                for (int j = 0; j < 4; j++) fma2(acc[i][j], ad, bp[j]);
            }
        }
        __syncthreads();
    }

    // epilogue: optional RoPE, then store
    const int row0 = brow + ty * 8;
    const int col0 = bcol + tx * 8;
    const int f0 = (col0 & 63) >> 1;   // freq index base; col pairs are (even, odd)

#pragma unroll
    for (int i = 0; i < 8; i++) {
        int row = row0 + i;
        float o[8];
#pragma unroll
        for (int j = 0; j < 4; j++) {
            float2 t = upk(acc[i][j]);
            o[2 * j] = t.x; o[2 * j + 1] = t.y;
        }
        if (ROPE) {
            int l = row & lmask;
            const float* cb = cosT + (size_t)l * 32;
            const float* sb = sinT + (size_t)l * 32;
#pragma unroll
            for (int jp = 0; jp < 4; jp++) {
                float c = cb[f0 + jp], s = sb[f0 + jp];
                float xr = o[2 * jp], xi = o[2 * jp + 1];
                o[2 * jp]     = xr * c - xi * s;
                o[2 * jp + 1] = xr * s + xi * c;
            }
        }
        float4* cp = (float4*)(C + (size_t)row * N + col0);
        cp[0] = make_float4(o[0], o[1], o[2], o[3]);
        cp[1] = make_float4(o[4], o[5], o[6], o[7]);
    }
}

// ---------------- projection: Kp[b,h,p,d] = sum_{l<=p} kpm[p,l] * KF[b,l,h*64+d] ----------------
// grid = B*H blocks, 256 threads. Thread = (p = tid&127, half = tid>>7 -> 32 of 64 dims).
__global__ __launch_bounds__(256)
void proj_kernel(const float* __restrict__ Kf, const float* __restrict__ Vf,
                 const float* __restrict__ kpm, const float* __restrict__ vpm,
                 float* __restrict__ Kp, float* __restrict__ Vp)
{
    __shared__ float s[PDIM][HDIM + 4];
    const int bh = blockIdx.x;
    const int b = bh >> 4, h = bh & 15;
    const int tid = threadIdx.x;
    const int p = tid & 127;
    const int half = tid >> 7;

#pragma unroll 1
    for (int phase = 0; phase < 2; phase++) {
        const float* src = phase == 0 ? Kf : Vf;
        const float* pm  = phase == 0 ? kpm : vpm;
        float* dst_base  = phase == 0 ? Kp : Vp;

        for (int i = tid; i < PDIM * (HDIM / 4); i += 256) {
            int l = i >> 4, c4 = (i & 15) * 4;
            float4 v = *(const float4*)(src + ((size_t)(b * 128 + l)) * DIM + h * HDIM + c4);
            s[l][c4] = v.x; s[l][c4 + 1] = v.y; s[l][c4 + 2] = v.z; s[l][c4 + 3] = v.w;
        }
        __syncthreads();

        float4 acc[8];
#pragma unroll
        for (int j = 0; j < 8; j++) acc[j] = make_float4(0.f, 0.f, 0.f, 0.f);

        for (int lc = 0; lc <= p; lc++) {
            float wv = pm[(size_t)p * 4096 + lc];
#pragma unroll
            for (int j = 0; j < 8; j++) {
                float4 kv = *(const float4*)&s[lc][half * 32 + j * 4];
                acc[j].x += wv * kv.x; acc[j].y += wv * kv.y;
                acc[j].z += wv * kv.z; acc[j].w += wv * kv.w;
            }
        }
        float* dst = dst_base + ((size_t)bh * PDIM + p) * HDIM + half * 32;
#pragma unroll
        for (int j = 0; j < 8; j++) *(float4*)(dst + j * 4) = acc[j];
        __syncthreads();
    }
}

// ---------------- attention: per-thread query row, w[128] in registers ----------------
// grid = B*H*(L/256), block = 256 threads.
__global__ __launch_bounds__(256, 1)
void attn_kernel(const float* __restrict__ Q, const float* __restrict__ Kp,
                 const float* __restrict__ Vp, float* __restrict__ O)
{
    __shared__ float s[PDIM][HDIM + 4];
    const int bid = blockIdx.x;
    const int ltile = bid & 15;         // L/256 = 16 tiles
    const int bh = bid >> 4;            // 0..63
    const int b = bh >> 4;
    const int h = bh & 15;
    const int tid = threadIdx.x;
    const int l = ltile * 256 + tid;
    const size_t qbase = ((size_t)(b * L_SEQ + l)) * DIM + h * HDIM;

    // stage Kp[bh] into smem
    for (int i = tid; i < PDIM * (HDIM / 4); i += 256) {
        int p = i >> 4, c4 = (i & 15) * 4;
        float4 v = *(const float4*)(Kp + ((size_t)bh * PDIM + p) * HDIM + c4);
        s[p][c4] = v.x; s[p][c4 + 1] = v.y; s[p][c4 + 2] = v.z; s[p][c4 + 3] = v.w;
    }
    __syncthreads();

    float w[PDIM];
#pragma unroll
    for (int p = 0; p < PDIM; p++) w[p] = 0.f;

    // scores: w[p] = q . Kp[p]
    for (int d4 = 0; d4 < HDIM / 4; d4++) {
        float4 q4 = *(const float4*)(Q + qbase + d4 * 4);
#pragma unroll
        for (int p = 0; p < PDIM; p++) {
            float4 k4 = *(const float4*)&s[p][d4 * 4];
            w[p] += q4.x * k4.x + q4.y * k4.y + q4.z * k4.z + q4.w * k4.w;
        }
    }

    // masked softmax over p (mask: p > l  -> -inf)
    float m = -1e30f;
#pragma unroll
    for (int p = 0; p < PDIM; p++) {
        w[p] = (p <= l) ? w[p] * 0.125f : -1e30f;
        m = fmaxf(m, w[p]);
    }
    float Z = 0.f;
#pragma unroll
    for (int p = 0; p < PDIM; p++) {
        float e = __expf(w[p] - m);
        w[p] = e;
        Z += e;
    }
    float inv = 1.0f / Z;
#pragma unroll
    for (int p = 0; p < PDIM; p++) w[p] *= inv;

    // stage Vp[bh] into smem (reuse)
    __syncthreads();
    for (int i = tid; i < PDIM * (HDIM / 4); i += 256) {
        int p = i >> 4, c4 = (i & 15) * 4;
        float4 v = *(const float4*)(Vp + ((size_t)bh * PDIM + p) * HDIM + c4);
        s[p][c4] = v.x; s[p][c4 + 1] = v.y; s[p][c4 + 2] = v.z; s[p][c4 + 3] = v.w;
    }
    __syncthreads();

    // out = w . Vp
    for (int d4 = 0; d4 < HDIM / 4; d4++) {
        float4 o = make_float4(0.f, 0.f, 0.f, 0.f);
#pragma unroll
        for (int p = 0; p < PDIM; p++) {
            float4 v4 = *(const float4*)&s[p][d4 * 4];
            o.x += w[p] * v4.x; o.y += w[p] * v4.y;
            o.z += w[p] * v4.z; o.w += w[p] * v4.w;
        }
        *(float4*)(O + qbase + d4 * 4) = o;
    }
}

// ---------------- launch ----------------
extern "C" void kernel_launch(void* const* d_in, const int* in_sizes, int n_in,
                              void* d_out, int out_size)
{
    const float* x   = (const float*)d_in[0];
    const float* fc  = (const float*)d_in[1];
    const float* fs  = (const float*)d_in[2];
    const float* Wq  = (const float*)d_in[3];
    const float* Wk  = (const float*)d_in[4];
    const float* Wv  = (const float*)d_in[5];
    const float* Wo  = (const float*)d_in[6];
    const float* kpm = (const float*)d_in[7];
    const float* vpm = (const float*)d_in[8];
    float* out = (float*)d_out;

    // resolve scratch symbol addresses once (first call is the non-captured
    // correctness run; capture call then performs kernel launches only)
    static float *pQ = nullptr, *pKF, *pVF, *pKp, *pVp, *pAT;
    if (!pQ) {
        cudaGetSymbolAddress((void**)&pKF, g_KF);
        cudaGetSymbolAddress((void**)&pVF, g_VF);
        cudaGetSymbolAddress((void**)&pKp, g_Kp);
        cudaGetSymbolAddress((void**)&pVp, g_Vp);
        cudaGetSymbolAddress((void**)&pAT, g_AT);
        cudaGetSymbolAddress((void**)&pQ,  g_Q);   // set last: acts as the init flag
    }

    const int Mq = BATCH * L_SEQ;      // 16384
    const int Mkv = BATCH * 128;       // 512

    // 1) Q = rope(x @ Wq^T)
    sgemm_nt<1, 0><<<dim3(DIM / BN, Mq / BM), 256>>>(x, Wq, pQ, Mq, DIM, DIM, fc, fs, L_SEQ - 1);
    // 2) K (first 128 tokens per batch) = rope(x128 @ Wk^T)
    sgemm_nt<1, 1><<<dim3(DIM / BN, Mkv / BM), 256>>>(x, Wk, pKF, Mkv, DIM, DIM, fc, fs, 127);
    // 3) V (first 128 tokens per batch) = x128 @ Wv^T
    sgemm_nt<0, 1><<<dim3(DIM / BN, Mkv / BM), 256>>>(x, Wv, pVF, Mkv, DIM, DIM, nullptr, nullptr, 0);
    // 4) causal-masked low-rank projections
    proj_kernel<<<BATCH * NHEAD, 256>>>(pKF, pVF, kpm, vpm, pKp, pVp);
    // 5) attention
    attn_kernel<<<BATCH * NHEAD * (L_SEQ / 256), 256>>>(pQ, pKp, pVp, pAT);
    // 6) out = attn @ Wo^T
    sgemm_nt<0, 0><<<dim3(DIM / BN, Mq / BM), 256>>>(pAT, Wo, out, Mq, DIM, DIM, nullptr, nullptr, 0);
}

// round 4
// speedup vs baseline: 2.0767x; 2.0767x over previous
#include <cuda_runtime.h>
#include <cuda_bf16.h>
#include <cstdint>

typedef unsigned long long ull;

#define L_SEQ 4096
#define DIM   1024
#define NHEAD 16
#define HDIM  64
#define PDIM  128
#define BATCH 4

// ================= scratch (device globals; no allocation allowed) =================
__device__ __nv_bfloat16 g_xh [(size_t)BATCH * L_SEQ * DIM];
__device__ __nv_bfloat16 g_xl [(size_t)BATCH * L_SEQ * DIM];
__device__ __nv_bfloat16 g_Wqh[DIM * DIM], g_Wql[DIM * DIM];
__device__ __nv_bfloat16 g_Wkh[DIM * DIM], g_Wkl[DIM * DIM];
__device__ __nv_bfloat16 g_Wvh[DIM * DIM], g_Wvl[DIM * DIM];
__device__ __nv_bfloat16 g_Woh[DIM * DIM], g_Wol[DIM * DIM];
__device__ float g_Q [(size_t)BATCH * L_SEQ * DIM];
__device__ float g_KF[BATCH * 128 * DIM];
__device__ float g_VF[BATCH * 128 * DIM];
__device__ float g_Kp[BATCH * NHEAD * PDIM * HDIM];
__device__ float g_Vp[BATCH * NHEAD * PDIM * HDIM];
__device__ __nv_bfloat16 g_ATh[(size_t)BATCH * L_SEQ * DIM];
__device__ __nv_bfloat16 g_ATl[(size_t)BATCH * L_SEQ * DIM];

// ================= helpers =================
__device__ __forceinline__ uint32_t smem_u32(const void* p) {
    uint32_t a;
    asm("{ .reg .u64 t; cvta.to.shared.u64 t, %1; cvt.u32.u64 %0, t; }" : "=r"(a) : "l"(p));
    return a;
}
__device__ __forceinline__ uint32_t pkbf(__nv_bfloat16 a, __nv_bfloat16 b) {
    return (uint32_t)__bfloat16_as_ushort(a) | ((uint32_t)__bfloat16_as_ushort(b) << 16);
}

#define CP_ASYNC16(d, g) asm volatile("cp.async.cg.shared.global [%0], [%1], 16;\n" :: "r"(d), "l"(g) : "memory")
#define CP_COMMIT()      asm volatile("cp.async.commit_group;\n" ::: "memory")
#define CP_WAIT(n)       asm volatile("cp.async.wait_group %0;\n" :: "n"(n) : "memory")

__device__ __forceinline__ void ldsm_x4(uint32_t* r, uint32_t addr) {
    asm volatile("ldmatrix.sync.aligned.m8n8.x4.shared.b16 {%0,%1,%2,%3}, [%4];"
        : "=r"(r[0]), "=r"(r[1]), "=r"(r[2]), "=r"(r[3]) : "r"(addr));
}
__device__ __forceinline__ void mma16816(float* c, const uint32_t* a, const uint32_t* b) {
    asm volatile("mma.sync.aligned.m16n8k16.row.col.f32.bf16.bf16.f32 "
        "{%0,%1,%2,%3}, {%4,%5,%6,%7}, {%8,%9}, {%0,%1,%2,%3};"
        : "+f"(c[0]), "+f"(c[1]), "+f"(c[2]), "+f"(c[3])
        : "r"(a[0]), "r"(a[1]), "r"(a[2]), "r"(a[3]), "r"(b[0]), "r"(b[1]));
}

// ================= hi/lo bf16 split =================
__global__ void split_bf16(const float4* __restrict__ src, uint2* __restrict__ hi,
                           uint2* __restrict__ lo, int n4)
{
    int i = blockIdx.x * blockDim.x + threadIdx.x;
    if (i >= n4) return;
    float4 v = src[i];
    __nv_bfloat16 h0 = __float2bfloat16_rn(v.x), h1 = __float2bfloat16_rn(v.y);
    __nv_bfloat16 h2 = __float2bfloat16_rn(v.z), h3 = __float2bfloat16_rn(v.w);
    __nv_bfloat16 l0 = __float2bfloat16_rn(v.x - __bfloat162float(h0));
    __nv_bfloat16 l1 = __float2bfloat16_rn(v.y - __bfloat162float(h1));
    __nv_bfloat16 l2 = __float2bfloat16_rn(v.z - __bfloat162float(h2));
    __nv_bfloat16 l3 = __float2bfloat16_rn(v.w - __bfloat162float(h3));
    hi[i] = make_uint2(pkbf(h0, h1), pkbf(h2, h3));
    lo[i] = make_uint2(pkbf(l0, l1), pkbf(l2, l3));
}

// ================= HMMA split-GEMM: C[M,N] = (Ah+Al) @ (Bh+Bl)^T (drop Al*Bl) =================
// CTA tile 128x128, BK=32. 8 warps: wm = wid&1 (2x M64), wn = wid>>1 (4x N32).
// smem tiles 128 rows x 64B, XOR swizzle on 16B chunks: c ^= (row>>1)&3.
constexpr int TILE_BYTES  = 128 * 64;          // 8 KB
constexpr int STAGE_BYTES = 4 * TILE_BYTES;    // Ah, Al, Bh, Bl
constexpr int HM_SMEM     = 2 * STAGE_BYTES;   // 64 KB

// A-operand ldmatrix.x4 addresses: matrices = (rows0-7,k0) (rows8-15,k0) (rows0-7,k1) (rows8-15,k1)
__device__ __forceinline__ uint32_t a_addr(uint32_t tb, int row0, int kk, int lane) {
    int row = row0 + (lane & 15);
    int c = (2 * kk + (lane >> 4)) ^ ((row >> 1) & 3);
    return tb + row * 64 + c * 16;
}
// B-operand ldmatrix.x4 (non-trans) addresses: matrices = (n0-7,k0) (n0-7,k1) (n8-15,k0) (n8-15,k1)
__device__ __forceinline__ uint32_t b_addr(uint32_t tb, int n0, int kk, int lane) {
    int g = lane >> 3, lr = lane & 7;
    int n = n0 + lr + (g >> 1) * 8;
    int c = (2 * kk + (g & 1)) ^ ((n >> 1) & 3);
    return tb + n * 64 + c * 16;
}

template<int GATHER>
__device__ __forceinline__ void hm_load(uint32_t stb,
    const __nv_bfloat16* Ah, const __nv_bfloat16* Al,
    const __nv_bfloat16* Bh, const __nv_bfloat16* Bl,
    int brow, int bcol, int kofs, int K, int tid)
{
#pragma unroll
    for (int t = 0; t < 4; t++) {
        const __nv_bfloat16* src = (t == 0) ? Ah : (t == 1) ? Al : (t == 2) ? Bh : Bl;
        int r0 = (t < 2) ? brow : bcol;
#pragma unroll
        for (int i = 0; i < 2; i++) {
            int id = tid + i * 256;          // 0..511
            int row = id >> 2, c = id & 3;
            int gr = r0 + row;
            if (GATHER && t < 2) gr = (gr >> 7) * L_SEQ + (gr & 127);
            const void* g = src + (size_t)gr * K + kofs + c * 8;
            uint32_t d = stb + t * TILE_BYTES + row * 64 + ((c ^ ((row >> 1) & 3)) * 16);
            CP_ASYNC16(d, g);
        }
    }
}

template<int ROPE, int GATHER>
__global__ __launch_bounds__(256, 2)
void hmma_gemm(const __nv_bfloat16* __restrict__ Ah, const __nv_bfloat16* __restrict__ Al,
               const __nv_bfloat16* __restrict__ Bh, const __nv_bfloat16* __restrict__ Bl,
               float* __restrict__ C, int M, int N, int K,
               const float* __restrict__ cosT, const float* __restrict__ sinT, int lmask)
{
    extern __shared__ __align__(128) char smem[];
    uint32_t sb = smem_u32(smem);
    const int tid = threadIdx.x;
    const int lane = tid & 31;
    const int wid = tid >> 5;
    const int wm = wid & 1, wn = wid >> 1;
    const int brow = blockIdx.y * 128, bcol = blockIdx.x * 128;

    float acc[4][4][4];
#pragma unroll
    for (int a = 0; a < 4; a++)
#pragma unroll
        for (int b = 0; b < 4; b++)
#pragma unroll
            for (int c = 0; c < 4; c++) acc[a][b][c] = 0.f;

    const int NIT = K / 32;    // 32
    hm_load<GATHER>(sb, Ah, Al, Bh, Bl, brow, bcol, 0, K, tid);
    CP_COMMIT();
    hm_load<GATHER>(sb + STAGE_BYTES, Ah, Al, Bh, Bl, brow, bcol, 32, K, tid);
    CP_COMMIT();

    for (int it = 0; it < NIT; it++) {
        int s = it & 1;
        CP_WAIT(1);
        __syncthreads();
        uint32_t stb = sb + s * STAGE_BYTES;
#pragma unroll
        for (int kk = 0; kk < 2; kk++) {
            uint32_t af[16], bhf[8], blf[8];
#pragma unroll
            for (int mt = 0; mt < 4; mt++)
                ldsm_x4(af + mt * 4, a_addr(stb, wm * 64 + mt * 16, kk, lane));
#pragma unroll
            for (int np = 0; np < 2; np++)
                ldsm_x4(bhf + np * 4, b_addr(stb + 2 * TILE_BYTES, wn * 32 + np * 16, kk, lane));
#pragma unroll
            for (int np = 0; np < 2; np++)
                ldsm_x4(blf + np * 4, b_addr(stb + 3 * TILE_BYTES, wn * 32 + np * 16, kk, lane));
#pragma unroll
            for (int mt = 0; mt < 4; mt++)
#pragma unroll
                for (int nt = 0; nt < 4; nt++) {
                    const uint32_t* bp = bhf + (nt >> 1) * 4 + (nt & 1) * 2;
                    const uint32_t* lp = blf + (nt >> 1) * 4 + (nt & 1) * 2;
                    mma16816(acc[mt][nt], af + mt * 4, bp);
                    mma16816(acc[mt][nt], af + mt * 4, lp);
                }
            // reload Al over af, multiply against Bh
#pragma unroll
            for (int mt = 0; mt < 4; mt++)
                ldsm_x4(af + mt * 4, a_addr(stb + TILE_BYTES, wm * 64 + mt * 16, kk, lane));
#pragma unroll
            for (int mt = 0; mt < 4; mt++)
#pragma unroll
                for (int nt = 0; nt < 4; nt++)
                    mma16816(acc[mt][nt], af + mt * 4, bhf + (nt >> 1) * 4 + (nt & 1) * 2);
        }
        __syncthreads();
        if (it + 2 < NIT)
            hm_load<GATHER>(sb + s * STAGE_BYTES, Ah, Al, Bh, Bl, brow, bcol, (it + 2) * 32, K, tid);
        CP_COMMIT();   // empty group when no load keeps wait-count arithmetic valid
    }

    // epilogue: optional RoPE, store fp32
    const int gr_ = lane >> 2, gc = (lane & 3) * 2;
#pragma unroll
    for (int mt = 0; mt < 4; mt++) {
        int r0 = brow + wm * 64 + mt * 16 + gr_;
#pragma unroll
        for (int nt = 0; nt < 4; nt++) {
            int col = bcol + wn * 32 + nt * 8 + gc;
            float c0 = acc[mt][nt][0], c1 = acc[mt][nt][1];
            float c2 = acc[mt][nt][2], c3 = acc[mt][nt][3];
            if (ROPE) {
                int f = (col & 63) >> 1;
                int l0 = r0 & lmask;
                float cc = cosT[l0 * 32 + f], ss = sinT[l0 * 32 + f];
                float t0 = c0 * cc - c1 * ss, t1 = c0 * ss + c1 * cc;
                c0 = t0; c1 = t1;
                int l1 = (r0 + 8) & lmask;
                cc = cosT[l1 * 32 + f]; ss = sinT[l1 * 32 + f];
                t0 = c2 * cc - c3 * ss; t1 = c2 * ss + c3 * cc;
                c2 = t0; c3 = t1;
            }
            *(float2*)(C + (size_t)r0 * N + col)       = make_float2(c0, c1);
            *(float2*)(C + (size_t)(r0 + 8) * N + col) = make_float2(c2, c3);
        }
    }
}

// ================= projection: Kp[b,h,p,d] = sum_{l<=p} kpm[p,l]*KF[b,l,h*64+d] =================
__global__ __launch_bounds__(256)
void proj_kernel(const float* __restrict__ Kf, const float* __restrict__ Vf,
                 const float* __restrict__ kpm, const float* __restrict__ vpm,
                 float* __restrict__ Kp, float* __restrict__ Vp)
{
    __shared__ float s[PDIM][HDIM + 4];
    const int bh = blockIdx.x;
    const int b = bh >> 4, h = bh & 15;
    const int tid = threadIdx.x;
    const int p = tid & 127;
    const int half = tid >> 7;

#pragma unroll 1
    for (int phase = 0; phase < 2; phase++) {
        const float* src = phase == 0 ? Kf : Vf;
        const float* pm  = phase == 0 ? kpm : vpm;
        float* dst_base  = phase == 0 ? Kp : Vp;

        for (int i = tid; i < PDIM * (HDIM / 4); i += 256) {
            int l = i >> 4, c4 = (i & 15) * 4;
            float4 v = *(const float4*)(src + ((size_t)(b * 128 + l)) * DIM + h * HDIM + c4);
            s[l][c4] = v.x; s[l][c4 + 1] = v.y; s[l][c4 + 2] = v.z; s[l][c4 + 3] = v.w;
        }
        __syncthreads();

        float4 acc[8];
#pragma unroll
        for (int j = 0; j < 8; j++) acc[j] = make_float4(0.f, 0.f, 0.f, 0.f);

        for (int lc = 0; lc <= p; lc++) {
            float wv = pm[(size_t)p * 4096 + lc];
#pragma unroll
            for (int j = 0; j < 8; j++) {
                float4 kv = *(const float4*)&s[lc][half * 32 + j * 4];
                acc[j].x += wv * kv.x; acc[j].y += wv * kv.y;
                acc[j].z += wv * kv.z; acc[j].w += wv * kv.w;
            }
        }
        float* dst = dst_base + ((size_t)bh * PDIM + p) * HDIM + half * 32;
#pragma unroll
        for (int j = 0; j < 8; j++) *(float4*)(dst + j * 4) = acc[j];
        __syncthreads();
    }
}

// ================= attention (round-1 verified math, bf16 hi/lo output) =================
__global__ __launch_bounds__(256, 1)
void attn_kernel(const float* __restrict__ Q, const float* __restrict__ Kp,
                 const float* __restrict__ Vp,
                 __nv_bfloat16* __restrict__ Oh, __nv_bfloat16* __restrict__ Ol)
{
    __shared__ float s[PDIM][HDIM + 4];
    const int bid = blockIdx.x;
    const int ltile = bid & 15;
    const int bh = bid >> 4;
    const int b = bh >> 4;
    const int h = bh & 15;
    const int tid = threadIdx.x;
    const int l = ltile * 256 + tid;
    const size_t qbase = ((size_t)(b * L_SEQ + l)) * DIM + h * HDIM;

    for (int i = tid; i < PDIM * (HDIM / 4); i += 256) {
        int p = i >> 4, c4 = (i & 15) * 4;
        float4 v = *(const float4*)(Kp + ((size_t)bh * PDIM + p) * HDIM + c4);
        s[p][c4] = v.x; s[p][c4 + 1] = v.y; s[p][c4 + 2] = v.z; s[p][c4 + 3] = v.w;
    }
    __syncthreads();

    float w[PDIM];
#pragma unroll
    for (int p = 0; p < PDIM; p++) w[p] = 0.f;

    for (int d4 = 0; d4 < HDIM / 4; d4++) {
        float4 q4 = *(const float4*)(Q + qbase + d4 * 4);
#pragma unroll
        for (int p = 0; p < PDIM; p++) {
            float4 k4 = *(const float4*)&s[p][d4 * 4];
            w[p] += q4.x * k4.x + q4.y * k4.y + q4.z * k4.z + q4.w * k4.w;
        }
    }

    float m = -1e30f;
#pragma unroll
    for (int p = 0; p < PDIM; p++) {
        w[p] = (p <= l) ? w[p] * 0.125f : -1e30f;
        m = fmaxf(m, w[p]);
    }
    float Z = 0.f;
#pragma unroll
    for (int p = 0; p < PDIM; p++) {
        float e = __expf(w[p] - m);
        w[p] = e;
        Z += e;
    }
    float inv = 1.0f / Z;
#pragma unroll
    for (int p = 0; p < PDIM; p++) w[p] *= inv;

    __syncthreads();
    for (int i = tid; i < PDIM * (HDIM / 4); i += 256) {
        int p = i >> 4, c4 = (i & 15) * 4;
        float4 v = *(const float4*)(Vp + ((size_t)bh * PDIM + p) * HDIM + c4);
        s[p][c4] = v.x; s[p][c4 + 1] = v.y; s[p][c4 + 2] = v.z; s[p][c4 + 3] = v.w;
    }
    __syncthreads();

    for (int d4 = 0; d4 < HDIM / 4; d4++) {
        float4 o = make_float4(0.f, 0.f, 0.f, 0.f);
#pragma unroll
        for (int p = 0; p < PDIM; p++) {
            float4 v4 = *(const float4*)&s[p][d4 * 4];
            o.x += w[p] * v4.x; o.y += w[p] * v4.y;
            o.z += w[p] * v4.z; o.w += w[p] * v4.w;
        }
        __nv_bfloat16 h0 = __float2bfloat16_rn(o.x), h1 = __float2bfloat16_rn(o.y);
        __nv_bfloat16 h2 = __float2bfloat16_rn(o.z), h3 = __float2bfloat16_rn(o.w);
        __nv_bfloat16 e0 = __float2bfloat16_rn(o.x - __bfloat162float(h0));
        __nv_bfloat16 e1 = __float2bfloat16_rn(o.y - __bfloat162float(h1));
        __nv_bfloat16 e2 = __float2bfloat16_rn(o.z - __bfloat162float(h2));
        __nv_bfloat16 e3 = __float2bfloat16_rn(o.w - __bfloat162float(h3));
        *(uint2*)(Oh + qbase + d4 * 4) = make_uint2(pkbf(h0, h1), pkbf(h2, h3));
        *(uint2*)(Ol + qbase + d4 * 4) = make_uint2(pkbf(e0, e1), pkbf(e2, e3));
    }
}

// ================= launch =================
extern "C" void kernel_launch(void* const* d_in, const int* in_sizes, int n_in,
                              void* d_out, int out_size)
{
    const float* x   = (const float*)d_in[0];
    const float* fc  = (const float*)d_in[1];
    const float* fs  = (const float*)d_in[2];
    const float* Wq  = (const float*)d_in[3];
    const float* Wk  = (const float*)d_in[4];
    const float* Wv  = (const float*)d_in[5];
    const float* Wo  = (const float*)d_in[6];
    const float* kpm = (const float*)d_in[7];
    const float* vpm = (const float*)d_in[8];
    float* out = (float*)d_out;

    static bool inited = false;
    static __nv_bfloat16 *pxh, *pxl, *pWqh, *pWql, *pWkh, *pWkl, *pWvh, *pWvl, *pWoh, *pWol, *pATh, *pATl;
    static float *pQ, *pKF, *pVF, *pKp, *pVp;
    if (!inited) {
        cudaGetSymbolAddress((void**)&pxh,  g_xh);
        cudaGetSymbolAddress((void**)&pxl,  g_xl);
        cudaGetSymbolAddress((void**)&pWqh, g_Wqh); cudaGetSymbolAddress((void**)&pWql, g_Wql);
        cudaGetSymbolAddress((void**)&pWkh, g_Wkh); cudaGetSymbolAddress((void**)&pWkl, g_Wkl);
        cudaGetSymbolAddress((void**)&pWvh, g_Wvh); cudaGetSymbolAddress((void**)&pWvl, g_Wvl);
        cudaGetSymbolAddress((void**)&pWoh, g_Woh); cudaGetSymbolAddress((void**)&pWol, g_Wol);
        cudaGetSymbolAddress((void**)&pATh, g_ATh); cudaGetSymbolAddress((void**)&pATl, g_ATl);
        cudaGetSymbolAddress((void**)&pQ,  g_Q);
        cudaGetSymbolAddress((void**)&pKF, g_KF);
        cudaGetSymbolAddress((void**)&pVF, g_VF);
        cudaGetSymbolAddress((void**)&pKp, g_Kp);
        cudaGetSymbolAddress((void**)&pVp, g_Vp);
        cudaFuncSetAttribute(hmma_gemm<1,0>, cudaFuncAttributeMaxDynamicSharedMemorySize, HM_SMEM);
        cudaFuncSetAttribute(hmma_gemm<1,1>, cudaFuncAttributeMaxDynamicSharedMemorySize, HM_SMEM);
        cudaFuncSetAttribute(hmma_gemm<0,1>, cudaFuncAttributeMaxDynamicSharedMemorySize, HM_SMEM);
        cudaFuncSetAttribute(hmma_gemm<0,0>, cudaFuncAttributeMaxDynamicSharedMemorySize, HM_SMEM);
        inited = true;
    }

    const int Mq = BATCH * L_SEQ;                    // 16384
    const int n4x = (int)((size_t)Mq * DIM / 4);
    const int n4w = DIM * DIM / 4;

    split_bf16<<<n4x / 256, 256>>>((const float4*)x,  (uint2*)pxh,  (uint2*)pxl,  n4x);
    split_bf16<<<n4w / 256, 256>>>((const float4*)Wq, (uint2*)pWqh, (uint2*)pWql, n4w);
    split_bf16<<<n4w / 256, 256>>>((const float4*)Wk, (uint2*)pWkh, (uint2*)pWkl, n4w);
    split_bf16<<<n4w / 256, 256>>>((const float4*)Wv, (uint2*)pWvh, (uint2*)pWvl, n4w);
    split_bf16<<<n4w / 256, 256>>>((const float4*)Wo, (uint2*)pWoh, (uint2*)pWol, n4w);

    // Q = rope(x @ Wq^T)  [16384, 1024]
    hmma_gemm<1,0><<<dim3(DIM / 128, Mq / 128), 256, HM_SMEM>>>(
        pxh, pxl, pWqh, pWql, pQ, Mq, DIM, DIM, fc, fs, L_SEQ - 1);
    // K first-128 = rope(x128 @ Wk^T)  [512, 1024]
    hmma_gemm<1,1><<<dim3(DIM / 128, (BATCH * 128) / 128), 256, HM_SMEM>>>(
        pxh, pxl, pWkh, pWkl, pKF, BATCH * 128, DIM, DIM, fc, fs, 127);
    // V first-128 = x128 @ Wv^T
    hmma_gemm<0,1><<<dim3(DIM / 128, (BATCH * 128) / 128), 256, HM_SMEM>>>(
        pxh, pxl, pWvh, pWvl, pVF, BATCH * 128, DIM, DIM, nullptr, nullptr, 0);
    // causal low-rank projections
    proj_kernel<<<BATCH * NHEAD, 256>>>(pKF, pVF, kpm, vpm, pKp, pVp);
    // attention -> bf16 hi/lo
    attn_kernel<<<BATCH * NHEAD * (L_SEQ / 256), 256>>>(pQ, pKp, pVp, pATh, pATl);
    // out = attn @ Wo^T
    hmma_gemm<0,0><<<dim3(DIM / 128, Mq / 128), 256, HM_SMEM>>>(
        pATh, pATl, pWoh, pWol, out, Mq, DIM, DIM, nullptr, nullptr, 0);
}